// round 1
// baseline (speedup 1.0000x reference)
#include <cuda_runtime.h>
#include <cuda_bf16.h>

#define TPB 256

// One corner evaluation. Accumulates the log terms (without ln2 factor) into T12
// and the signed atan value into T3.
//   bb, cc : corner b, c values
//   qb     : a^2 + bb^2   (precomputed, shared across 2 corners)
//   lb     : log2(qb)     (precomputed)
//   lc     : log2(a^2+cc^2) (precomputed)
#define CORNER(bb, cc, qb, lb, lc)                                          \
    {                                                                        \
        float s_  = fmaf((cc), (cc), (qb));      /* a^2+b^2+c^2 */           \
        float rs_ = rsqrtf(s_);                                              \
        float dl_ = s_ * rs_;                    /* delta */                 \
        float u1_ = fmaf(-0.5f, (lb), __log2f((cc) + dl_));                  \
        float u2_ = fmaf(-0.5f, (lc), __log2f((bb) + dl_));                  \
        T12 = fmaf((bb), u1_, T12);                                          \
        T12 = fmaf((cc), u2_, T12);                                          \
        float n_  = (bb) * (cc);                                             \
        float d_  = a * dl_;                                                 \
        float an_ = fabsf(n_), ad_ = fabsf(d_);                              \
        float mn_ = fminf(an_, ad_), mx_ = fmaxf(an_, ad_);                  \
        float t_  = __fdividef(mn_, mx_);        /* in [0,1] */              \
        float z_  = t_ * t_;                                                 \
        float p_  = fmaf(z_,  0.0028662257f, -0.0161657367f);                \
        p_ = fmaf(z_, p_,  0.0429096138f);                                   \
        p_ = fmaf(z_, p_, -0.0752896400f);                                   \
        p_ = fmaf(z_, p_,  0.1065626393f);                                   \
        p_ = fmaf(z_, p_, -0.1420889944f);                                   \
        p_ = fmaf(z_, p_,  0.1999355085f);                                   \
        p_ = fmaf(z_, p_, -0.3333314528f);                                   \
        float r_ = fmaf(t_ * z_, p_, t_);        /* atan(t), t<=1 */         \
        r_ = (an_ > ad_) ? (1.5707963267948966f - r_) : r_;                  \
        unsigned sgn_ = (__float_as_uint(n_) ^ __float_as_uint(d_)) & 0x80000000u; \
        T3 += __uint_as_float(__float_as_uint(r_) ^ sgn_);                   \
    }

__global__ __launch_bounds__(TPB)
void chiplet_thermal_kernel(const float* __restrict__ x,
                            const float* __restrict__ y,
                            const float* __restrict__ cx,
                            const float* __restrict__ cy,
                            const float* __restrict__ cw,
                            const float* __restrict__ ch,
                            const float* __restrict__ cp,
                            const float* __restrict__ Aptr,
                            const float* __restrict__ aptr,
                            const float* __restrict__ Bptr,
                            const float* __restrict__ lx,
                            const float* __restrict__ ly,
                            float* __restrict__ out,
                            int N, int G2)
{
    extern __shared__ float sh[];
    float* s_cx  = sh;
    float* s_cy  = s_cx  + N;
    float* s_w2  = s_cy  + N;
    float* s_h2  = s_w2  + N;
    float* s_pa  = s_h2  + N;
    float* s_rlx = s_pa  + N;
    float* s_rly = s_rlx + N;

    const int bi = blockIdx.y;
    const float A    = Aptr[0];
    const float a    = aptr[0];
    const float Boff = Bptr[0];
    const float K    = 1.1283791670955126f;   // 2/sqrt(pi)

    for (int i = threadIdx.x; i < N; i += TPB) {
        s_cx[i]  = cx[bi * N + i];
        s_cy[i]  = cy[bi * N + i];
        s_w2[i]  = 0.5f * cw[bi * N + i];
        s_h2[i]  = 0.5f * ch[bi * N + i];
        s_pa[i]  = cp[bi * N + i] * A * K;     // P_i * A * (2/sqrt(pi))
        s_rlx[i] = 1.0f / lx[i];
        s_rly[i] = 1.0f / ly[i];
    }
    __syncthreads();

    const int g = blockIdx.x * TPB + threadIdx.x;
    if (g >= G2) return;
    const long long idx = (long long)bi * G2 + g;

    const float xv    = x[idx];
    const float yv    = y[idx];
    const float a2    = a * a;
    const float boffK = Boff * 0.8862269254527580f;  // Boff * sqrt(pi)/2 = Boff / K
    const float LN2   = 0.6931471805599453f;

    float acc = 0.0f;

    #pragma unroll 4
    for (int i = 0; i < N; ++i) {
        const float dx  = xv - s_cx[i];
        const float dy  = yv - s_cy[i];
        const float rlx = s_rlx[i], rly = s_rly[i];
        const float w2  = s_w2[i],  h2  = s_h2[i];

        const float b1 = (w2 - dx) * rlx;
        const float b2 = (w2 + dx) * rlx;
        const float c1 = (h2 - dy) * rly;
        const float c2 = (h2 + dy) * rly;

        const float qb1 = fmaf(b1, b1, a2);
        const float qb2 = fmaf(b2, b2, a2);
        const float qc1 = fmaf(c1, c1, a2);
        const float qc2 = fmaf(c2, c2, a2);

        const float lb1  = __log2f(qb1);
        const float lb2v = __log2f(qb2);
        const float lc1  = __log2f(qc1);
        const float lc2v = __log2f(qc2);

        float T12 = 0.0f, T3 = 0.0f;
        CORNER(b1, c1, qb1, lb1,  lc1);
        CORNER(b1, c2, qb1, lb1,  lc2v);
        CORNER(b2, c1, qb2, lb2v, lc1);
        CORNER(b2, c2, qb2, lb2v, lc2v);

        // contribution = s_pa * (Boff/K + ln2*T12 - a*T3)
        float sumT = fmaf(LN2, T12, boffK);
        sumT = fmaf(-a, T3, sumT);
        acc  = fmaf(s_pa[i], sumT, acc);
    }

    out[idx] = acc;
}

extern "C" void kernel_launch(void* const* d_in, const int* in_sizes, int n_in,
                              void* d_out, int out_size)
{
    // Input order (metadata): x, y, chiplets_x, chiplets_y, chiplets_width,
    // chiplets_height, chiplets_power, A, a, B_off, lx, ly, grid
    const float* x  = (const float*)d_in[0];
    const float* y  = (const float*)d_in[1];
    const float* cx = (const float*)d_in[2];
    const float* cy = (const float*)d_in[3];
    const float* cw = (const float*)d_in[4];
    const float* ch = (const float*)d_in[5];
    const float* cp = (const float*)d_in[6];
    const float* A  = (const float*)d_in[7];
    const float* a  = (const float*)d_in[8];
    const float* B  = (const float*)d_in[9];
    const float* lx = (const float*)d_in[10];
    const float* ly = (const float*)d_in[11];

    const int N  = in_sizes[10];                 // lx has N elements
    const int Bn = in_sizes[2] / N;              // chiplets_x is B*N
    const int G2 = in_sizes[0] / Bn;             // x is B*G2

    dim3 grid((G2 + TPB - 1) / TPB, Bn);
    size_t shmem = (size_t)7 * N * sizeof(float);
    chiplet_thermal_kernel<<<grid, TPB, shmem>>>(x, y, cx, cy, cw, ch, cp,
                                                 A, a, B, lx, ly,
                                                 (float*)d_out, N, G2);
}

// round 3
// speedup vs baseline: 1.0050x; 1.0050x over previous
#include <cuda_runtime.h>
#include <cuda_bf16.h>

#define TPB 256
typedef unsigned long long u64;

// ---- packed f32x2 helpers (Blackwell sm_103a) ----
__device__ __forceinline__ u64 pk(float lo, float hi) {
    u64 r; asm("mov.b64 %0, {%1,%2};" : "=l"(r) : "f"(lo), "f"(hi)); return r;
}
__device__ __forceinline__ void upk(u64 v, float& lo, float& hi) {
    asm("mov.b64 {%0,%1}, %2;" : "=f"(lo), "=f"(hi) : "l"(v));
}
__device__ __forceinline__ u64 f2fma(u64 a, u64 b, u64 c) {
    u64 d; asm("fma.rn.f32x2 %0, %1, %2, %3;" : "=l"(d) : "l"(a), "l"(b), "l"(c)); return d;
}
__device__ __forceinline__ u64 f2mul(u64 a, u64 b) {
    u64 d; asm("mul.rn.f32x2 %0, %1, %2;" : "=l"(d) : "l"(a), "l"(b)); return d;
}
__device__ __forceinline__ u64 f2add(u64 a, u64 b) {
    u64 d; asm("add.rn.f32x2 %0, %1, %2;" : "=l"(d) : "l"(a), "l"(b)); return d;
}
// ---- guaranteed single-MUFU transcendentals ----
__device__ __forceinline__ float lg2a(float x) { float r; asm("lg2.approx.f32 %0, %1;"   : "=f"(r) : "f"(x)); return r; }
__device__ __forceinline__ float rsqa(float x) { float r; asm("rsqrt.approx.f32 %0, %1;" : "=f"(r) : "f"(x)); return r; }
__device__ __forceinline__ float rcpa(float x) { float r; asm("rcp.approx.f32 %0, %1;"   : "=f"(r) : "f"(x)); return r; }

// One corner for a PAIR of grid elements.
// bb, cc: packed b,c. qb: packed a^2+b^2. lb, lc: packed log2(a^2+b^2), log2(a^2+c^2).
// Accumulates log-terms (log2 units) into T12 and signed atan into T3_0/T3_1.
// atan: deg-17 odd minimax on [0,1] (verified in R1, rel_err ~1e-6).
#define CORNER_PAIR(bb, cc, qb, lb, lc)                                          \
    {                                                                            \
        u64 s_   = f2fma((cc), (cc), (qb));                                      \
        float s0_, s1_;  upk(s_, s0_, s1_);                                      \
        float dl0_ = s0_ * rsqa(s0_);                                            \
        float dl1_ = s1_ * rsqa(s1_);                                            \
        u64 dl_  = pk(dl0_, dl1_);                                               \
        u64 cpd_ = f2add((cc), dl_);                                             \
        u64 bpd_ = f2add((bb), dl_);                                             \
        float cp0_, cp1_, bp0_, bp1_;                                            \
        upk(cpd_, cp0_, cp1_);  upk(bpd_, bp0_, bp1_);                           \
        u64 l1_ = pk(lg2a(cp0_), lg2a(cp1_));                                    \
        u64 l2_ = pk(lg2a(bp0_), lg2a(bp1_));                                    \
        u64 u1_ = f2fma((lb), MHALF, l1_);                                       \
        u64 u2_ = f2fma((lc), MHALF, l2_);                                       \
        T12 = f2fma((bb), u1_, T12);                                             \
        T12 = f2fma((cc), u2_, T12);                                             \
        u64 nn_ = f2mul((bb), (cc));                                             \
        u64 dd_ = f2mul(APK, dl_);                                               \
        float n0_, n1_, d0_, d1_;                                                \
        upk(nn_, n0_, n1_);  upk(dd_, d0_, d1_);                                 \
        float an0_ = fabsf(n0_), ad0_ = fabsf(d0_);                              \
        float an1_ = fabsf(n1_), ad1_ = fabsf(d1_);                              \
        float mn0_ = fminf(an0_, ad0_), mx0_ = fmaxf(an0_, ad0_);                \
        float mn1_ = fminf(an1_, ad1_), mx1_ = fmaxf(an1_, ad1_);                \
        u64 t_ = pk(mn0_ * rcpa(mx0_), mn1_ * rcpa(mx1_));                       \
        u64 z_ = f2mul(t_, t_);                                                  \
        u64 p_ = f2fma(z_, C17, C15);                                            \
        p_ = f2fma(z_, p_, C13);                                                 \
        p_ = f2fma(z_, p_, C11);                                                 \
        p_ = f2fma(z_, p_, C9);                                                  \
        p_ = f2fma(z_, p_, C7);                                                  \
        p_ = f2fma(z_, p_, C5);                                                  \
        p_ = f2fma(z_, p_, C3);                                                  \
        u64 tz_ = f2mul(t_, z_);                                                 \
        u64 r_  = f2fma(tz_, p_, t_);       /* atan(t), t in [0,1] */            \
        u64 rr_ = f2fma(r_, MONE, PIO2P);   /* pi/2 - r */                       \
        float r0_, r1_, q0_, q1_;                                                \
        upk(r_, r0_, r1_);  upk(rr_, q0_, q1_);                                  \
        float v0_ = (an0_ > ad0_) ? q0_ : r0_;                                   \
        float v1_ = (an1_ > ad1_) ? q1_ : r1_;                                   \
        unsigned sg0_ = (__float_as_uint(n0_) ^ __float_as_uint(d0_)) & 0x80000000u; \
        unsigned sg1_ = (__float_as_uint(n1_) ^ __float_as_uint(d1_)) & 0x80000000u; \
        T3_0 += __uint_as_float(__float_as_uint(v0_) ^ sg0_);                    \
        T3_1 += __uint_as_float(__float_as_uint(v1_) ^ sg1_);                    \
    }

__global__ __launch_bounds__(TPB, 3)
void chiplet_thermal_kernel(const float* __restrict__ x,
                            const float* __restrict__ y,
                            const float* __restrict__ cx,
                            const float* __restrict__ cy,
                            const float* __restrict__ cw,
                            const float* __restrict__ ch,
                            const float* __restrict__ cp,
                            const float* __restrict__ Aptr,
                            const float* __restrict__ aptr,
                            const float* __restrict__ Bptr,
                            const float* __restrict__ lx,
                            const float* __restrict__ ly,
                            float* __restrict__ out,
                            int N, int G2)
{
    // Per-chiplet params stored as DUPLICATED pairs {v,v} so an LDS.64 yields a
    // ready packed f32x2 operand: layout = 8 u64 (16 floats) per chiplet.
    extern __shared__ __align__(16) float sh[];

    const int bi = blockIdx.y;
    const float A    = Aptr[0];
    const float a    = aptr[0];
    const float Boff = Bptr[0];
    const float K    = 1.1283791670955126f;   // 2/sqrt(pi)

    for (int i = threadIdx.x; i < N; i += TPB) {
        float rlx = 1.0f / lx[i];
        float rly = 1.0f / ly[i];
        float ncxr = -cx[bi * N + i] * rlx;
        float ncyr = -cy[bi * N + i] * rly;
        float w2r  = 0.5f * cw[bi * N + i] * rlx;
        float h2r  = 0.5f * ch[bi * N + i] * rly;
        float pa   = cp[bi * N + i] * A * K;
        float* p = sh + i * 16;
        p[0]  = ncxr; p[1]  = ncxr;
        p[2]  = ncyr; p[3]  = ncyr;
        p[4]  = w2r;  p[5]  = w2r;
        p[6]  = h2r;  p[7]  = h2r;
        p[8]  = rlx;  p[9]  = rlx;
        p[10] = rly;  p[11] = rly;
        p[12] = pa;   p[13] = pa;
        p[14] = 0.0f; p[15] = 0.0f;
    }
    __syncthreads();

    const int g = blockIdx.x * TPB + threadIdx.x;   // pair index
    const int halfG = G2 >> 1;
    if (g >= halfG) return;
    const long long idx2 = (long long)bi * halfG + g;

    const float2 xv = ((const float2*)x)[idx2];
    const float2 yv = ((const float2*)y)[idx2];
    const u64 xv2 = pk(xv.x, xv.y);
    const u64 yv2 = pk(yv.x, yv.y);

    // packed constants
    const float a2 = a * a;
    const u64 A2P   = pk(a2, a2);
    const u64 APK   = pk(a, a);
    const u64 MHALF = pk(-0.5f, -0.5f);
    const u64 MONE  = pk(-1.0f, -1.0f);
    const u64 PIO2P = pk(1.5707963267948966f, 1.5707963267948966f);
    // deg-17 odd minimax atan on [0,1] (same coefficients as the passing R1 kernel)
    const u64 C3  = pk(-0.3333314528f, -0.3333314528f);
    const u64 C5  = pk( 0.1999355085f,  0.1999355085f);
    const u64 C7  = pk(-0.1420889944f, -0.1420889944f);
    const u64 C9  = pk( 0.1065626393f,  0.1065626393f);
    const u64 C11 = pk(-0.0752896400f, -0.0752896400f);
    const u64 C13 = pk( 0.0429096138f,  0.0429096138f);
    const u64 C15 = pk(-0.0161657367f, -0.0161657367f);
    const u64 C17 = pk( 0.0028662257f,  0.0028662257f);
    const float LN2   = 0.6931471805599453f;
    const float boffK = Boff * 0.8862269254527580f;  // Boff * sqrt(pi)/2
    const u64 LN2P   = pk(LN2, LN2);
    const u64 BOFFKP = pk(boffK, boffK);
    const u64 NAP    = pk(-a, -a);

    u64 acc = pk(0.0f, 0.0f);

    #pragma unroll 4
    for (int i = 0; i < N; ++i) {
        const u64* cps = (const u64*)(sh + i * 16);
        const u64 ncxr = cps[0];
        const u64 ncyr = cps[1];
        const u64 w2r  = cps[2];
        const u64 h2r  = cps[3];
        const u64 rlx2 = cps[4];
        const u64 rly2 = cps[5];
        const u64 pa2  = cps[6];

        const u64 dxp = f2fma(xv2, rlx2, ncxr);   // (x - cx)/lx
        const u64 dyp = f2fma(yv2, rly2, ncyr);   // (y - cy)/ly
        const u64 b1  = f2fma(dxp, MONE, w2r);    // (w/2 - dx)/lx
        const u64 b2  = f2add(w2r, dxp);          // (w/2 + dx)/lx
        const u64 c1  = f2fma(dyp, MONE, h2r);
        const u64 c2  = f2add(h2r, dyp);

        const u64 qb1 = f2fma(b1, b1, A2P);
        const u64 qb2 = f2fma(b2, b2, A2P);
        const u64 qc1 = f2fma(c1, c1, A2P);
        const u64 qc2 = f2fma(c2, c2, A2P);

        float qa, qbv;
        upk(qb1, qa, qbv);  const u64 lb1 = pk(lg2a(qa), lg2a(qbv));
        upk(qb2, qa, qbv);  const u64 lb2 = pk(lg2a(qa), lg2a(qbv));
        upk(qc1, qa, qbv);  const u64 lc1 = pk(lg2a(qa), lg2a(qbv));
        upk(qc2, qa, qbv);  const u64 lc2 = pk(lg2a(qa), lg2a(qbv));

        u64 T12 = pk(0.0f, 0.0f);
        float T3_0 = 0.0f, T3_1 = 0.0f;

        CORNER_PAIR(b1, c1, qb1, lb1, lc1);
        CORNER_PAIR(b1, c2, qb1, lb1, lc2);
        CORNER_PAIR(b2, c1, qb2, lb2, lc1);
        CORNER_PAIR(b2, c2, qb2, lb2, lc2);

        // contribution = pa * (Boff/K + ln2*T12 - a*T3)
        u64 sumT = f2fma(LN2P, T12, BOFFKP);
        sumT = f2fma(NAP, pk(T3_0, T3_1), sumT);
        acc  = f2fma(pa2, sumT, acc);
    }

    float o0, o1;
    upk(acc, o0, o1);
    ((float2*)out)[idx2] = make_float2(o0, o1);
}

extern "C" void kernel_launch(void* const* d_in, const int* in_sizes, int n_in,
                              void* d_out, int out_size)
{
    // Input order: x, y, chiplets_x, chiplets_y, chiplets_width,
    // chiplets_height, chiplets_power, A, a, B_off, lx, ly, grid
    const float* x  = (const float*)d_in[0];
    const float* y  = (const float*)d_in[1];
    const float* cx = (const float*)d_in[2];
    const float* cy = (const float*)d_in[3];
    const float* cw = (const float*)d_in[4];
    const float* ch = (const float*)d_in[5];
    const float* cp = (const float*)d_in[6];
    const float* A  = (const float*)d_in[7];
    const float* a  = (const float*)d_in[8];
    const float* B  = (const float*)d_in[9];
    const float* lx = (const float*)d_in[10];
    const float* ly = (const float*)d_in[11];

    const int N  = in_sizes[10];                 // lx has N elements
    const int Bn = in_sizes[2] / N;              // chiplets_x is B*N
    const int G2 = in_sizes[0] / Bn;             // x is B*G2
    const int halfG = G2 >> 1;

    dim3 grid((halfG + TPB - 1) / TPB, Bn);
    size_t shmem = (size_t)16 * N * sizeof(float);
    chiplet_thermal_kernel<<<grid, TPB, shmem>>>(x, y, cx, cy, cw, ch, cp,
                                                 A, a, B, lx, ly,
                                                 (float*)d_out, N, G2);
}